// round 1
// baseline (speedup 1.0000x reference)
#include <cuda_runtime.h>
#include <cuda_bf16.h>

// Problem: gene_seq (N=256, M=2000) int32 in [0,4); embedding_mat (M=2000, 4, D=128) f32.
// out[n, m, :] = embedding_mat[m, gene_seq[n,m], :] / max(||.||, 1e-12)
//
// Strategy:
//   K1: precompute inv_norm for all 8000 (m, g) rows (one warp per row).
//   K2: one warp per (n, m) output row: lane loads float4 from table,
//       scales by inv_norm, stores float4 to out. Write-bound (~262 MB).

#define NM 256
#define MM 2000
#define DD 128
#define NROWS (MM * 4)   // 8000

__device__ float g_inv_norm[NROWS];

// ---------------- Kernel 1: inverse norms ----------------
// one warp per (m,g) row of 128 floats
__global__ void inv_norm_kernel(const float* __restrict__ emb) {
    int row = blockIdx.x * (blockDim.x >> 5) + (threadIdx.x >> 5);
    if (row >= NROWS) return;
    int lane = threadIdx.x & 31;

    const float4* p = reinterpret_cast<const float4*>(emb + (size_t)row * DD);
    float4 v = p[lane];
    float s = v.x * v.x + v.y * v.y + v.z * v.z + v.w * v.w;
    #pragma unroll
    for (int off = 16; off > 0; off >>= 1)
        s += __shfl_xor_sync(0xFFFFFFFFu, s, off);

    if (lane == 0) {
        float norm = sqrtf(s);
        norm = fmaxf(norm, 1e-12f);
        g_inv_norm[row] = 1.0f / norm;
    }
}

// ---------------- Kernel 2: gather + scale + store ----------------
// grid: (ceil(M/8), N), block: 256 threads = 8 warps.
// warp w of block (bx, n) handles m = bx*8 + w.
__global__ void __launch_bounds__(256) gather_kernel(
    const int* __restrict__ seq,
    const float* __restrict__ emb,
    float* __restrict__ out)
{
    int warp = threadIdx.x >> 5;
    int lane = threadIdx.x & 31;
    int m = blockIdx.x * 8 + warp;
    int n = blockIdx.y;
    if (m >= MM) return;

    int g = __ldg(seq + (size_t)n * MM + m);      // 0..3
    int row = m * 4 + g;
    float scale = g_inv_norm[row];

    const float4* src = reinterpret_cast<const float4*>(emb + (size_t)row * DD);
    float4 v = __ldg(src + lane);
    v.x *= scale; v.y *= scale; v.z *= scale; v.w *= scale;

    float4* dst = reinterpret_cast<float4*>(out + ((size_t)n * MM + m) * DD);
    dst[lane] = v;
}

extern "C" void kernel_launch(void* const* d_in, const int* in_sizes, int n_in,
                              void* d_out, int out_size) {
    const int*   seq = (const int*)d_in[0];     // (256, 2000) int32
    const float* emb = (const float*)d_in[1];   // (2000, 4, 128) f32
    float*       out = (float*)d_out;           // (256, 2000, 128) f32

    // K1: 8000 rows, 8 warps/block -> 1000 blocks
    inv_norm_kernel<<<1000, 256>>>(emb);

    // K2: grid (250, 256), 8 warps/block
    dim3 grid((MM + 7) / 8, NM);
    gather_kernel<<<grid, 256>>>(seq, emb, out);
}

// round 2
// speedup vs baseline: 1.3849x; 1.3849x over previous
#include <cuda_runtime.h>
#include <cuda_bf16.h>

// gene_seq (N=256, M=2000) int32 in [0,4); embedding_mat (M=2000, 4, D=128) f32.
// out[n, m, :] = embedding_mat[m, gene_seq[n,m], :] / max(||row||, 1e-12)
//
// Single kernel, tiled for table reuse:
//   block = 8 m's x 64 n's. Stage the 32 candidate rows (16KB) in smem,
//   normalize in-block, then stream 64 coalesced 512B stores per warp.
//   Writes (256MB) are the only large traffic -> HBM-write-bound.

#define NM 256
#define MM 2000
#define DD 128
#define MTILE 8
#define NTILE 64
#define NROWS_T (MTILE * 4)          // 32 rows per tile
#define ROW_F4 (DD / 4)              // 32 float4 per row
#define TILE_F4 (NROWS_T * ROW_F4)   // 1024 float4

__global__ void __launch_bounds__(256) embed_kernel(
    const int* __restrict__ seq,
    const float* __restrict__ emb,
    float* __restrict__ out)
{
    __shared__ float rows[NROWS_T * DD];     // 16 KB
    __shared__ float scales[NROWS_T];
    __shared__ int   sseq[NTILE][MTILE];     // 2 KB

    const int m0  = blockIdx.x * MTILE;
    const int n0  = blockIdx.y * NTILE;
    const int tid = threadIdx.x;
    const int warp = tid >> 5;
    const int lane = tid & 31;

    // --- stage 32 candidate rows (contiguous 16KB from emb + m0*4*128) ---
    const float4* src = reinterpret_cast<const float4*>(emb + (size_t)m0 * 4 * DD);
    float4* r4 = reinterpret_cast<float4*>(rows);
    #pragma unroll
    for (int i = 0; i < TILE_F4 / 256; i++)
        r4[tid + i * 256] = src[tid + i * 256];

    // --- stage seq tile: seq[n0+j][m0+mm], 64x8 ints ---
    #pragma unroll
    for (int i = 0; i < (NTILE * MTILE) / 256; i++) {
        int t  = tid + i * 256;
        int j  = t >> 3;
        int mm = t & 7;
        sseq[j][mm] = seq[(size_t)(n0 + j) * MM + m0 + mm];
    }
    __syncthreads();

    // --- norms: warp w handles rows w*4 .. w*4+3 ---
    #pragma unroll
    for (int i = 0; i < 4; i++) {
        int r = warp * 4 + i;
        float4 v = r4[r * ROW_F4 + lane];
        float s = v.x * v.x + v.y * v.y + v.z * v.z + v.w * v.w;
        #pragma unroll
        for (int off = 16; off > 0; off >>= 1)
            s += __shfl_xor_sync(0xFFFFFFFFu, s, off);
        if (lane == 0)
            scales[r] = 1.0f / fmaxf(sqrtf(s), 1e-12f);
    }
    __syncthreads();

    // --- rescale rows in place ---
    #pragma unroll
    for (int i = 0; i < TILE_F4 / 256; i++) {
        int si = tid + i * 256;
        float sc = scales[si >> 5];          // 32 float4 per row
        float4 v = r4[si];
        v.x *= sc; v.y *= sc; v.z *= sc; v.w *= sc;
        r4[si] = v;
    }
    __syncthreads();

    // --- stream outputs: warp w owns m = m0 + w, iterate 64 n's ---
    const int m = m0 + warp;
    float4* dst = reinterpret_cast<float4*>(out + ((size_t)n0 * MM + m) * DD);
    const size_t nstride = (size_t)MM * ROW_F4;   // float4 stride between n's

    #pragma unroll 4
    for (int j = 0; j < NTILE; j++) {
        int g = sseq[j][warp];                      // uniform broadcast LDS
        float4 v = r4[(warp * 4 + g) * ROW_F4 + lane];  // conflict-free 512B LDS
        dst[(size_t)j * nstride + lane] = v;        // coalesced STG.128
    }
}

extern "C" void kernel_launch(void* const* d_in, const int* in_sizes, int n_in,
                              void* d_out, int out_size) {
    const int*   seq = (const int*)d_in[0];     // (256, 2000) int32
    const float* emb = (const float*)d_in[1];   // (2000, 4, 128) f32
    float*       out = (float*)d_out;           // (256, 2000, 128) f32

    dim3 grid(MM / MTILE, NM / NTILE);          // (250, 4)
    embed_kernel<<<grid, 256>>>(seq, emb, out);
}